// round 2
// baseline (speedup 1.0000x reference)
#include <cuda_runtime.h>

// Phase vocoder time-stretch, rate = 0.9, phase_advance = 0.
// out[t] = mag[t] * U[t],  U[t] = prod_{k<=t} z[k]
//   z[0]   = s[0]/|s[0]|
//   z[t>0] = normalize( s[j+1] * conj(s[j]) ),  j = (int)((t-1)*0.9f)
//   mag[t] = a*|s[j1+1]| + (1-a)*|s[j1]|, j1=(int)(t*0.9f), a = frac
// Identical to exp(i*cumsum(wrapped phase diff))*mag with all atan2/sincos
// removed (cumulative product of unit rotations).

constexpr int Bb      = 16;
constexpr int Fb      = 1025;
constexpr int T       = 2048;
constexpr int TOUT    = 2276;          // ceil(2048 / 0.9)
constexpr int THREADS = 256;
constexpr int PER     = 9;             // 256 * 9 = 2304 >= 2276
constexpr float RATE  = 0.9f;

constexpr long long N_CPLX = (long long)Bb * Fb * TOUT;   // 37,326,400

__global__ __launch_bounds__(THREADS) void pv_kernel(
    const float* __restrict__ xr, const float* __restrict__ xi,
    float* __restrict__ out, int writeMode)   // 1 = interleaved float2, 0 = real-only float
{
    __shared__ float2 buf[2304];               // row staging (in), then output staging
    __shared__ float2 wscan[THREADS / 32];

    const int row = blockIdx.x;                // 0 .. B*F-1
    const float* __restrict__ rp = xr + (size_t)row * T;
    const float* __restrict__ ip = xi + (size_t)row * T;
    const int tid  = threadIdx.x;
    const int lane = tid & 31;
    const int warp = tid >> 5;

    // ---- load row into SMEM (scalar loads: alignment-proof, still coalesced) ----
    #pragma unroll
    for (int it = 0; it < T / THREADS; it++) {
        int idx = tid + it * THREADS;
        buf[idx] = make_float2(rp[idx], ip[idx]);
    }
    if (tid == 0) buf[T] = make_float2(0.f, 0.f);   // zero pad; only [T] ever read
    __syncthreads();

    // unit rotation z[t]
    auto zval = [&](int t, float& zr, float& zi) {
        if (t == 0) {
            float2 s = buf[0];
            float n2 = s.x * s.x + s.y * s.y;
            if (n2 > 0.f) { float inv = rsqrtf(n2); zr = s.x * inv; zi = s.y * inv; }
            else          { zr = 1.f; zi = 0.f; }
        } else {
            float ts = (float)(t - 1) * RATE;      // fp32, matches arange(0,T,rate)
            int j = (int)ts;
            float2 s0 = buf[j];
            float2 s1 = buf[j + 1];
            float pr = s1.x * s0.x + s1.y * s0.y;  // s1 * conj(s0)
            float pi = s1.y * s0.x - s1.x * s0.y;
            float n2 = pr * pr + pi * pi;
            if (n2 > 0.f) { float inv = rsqrtf(n2); zr = pr * inv; zi = pi * inv; }
            else          { zr = 1.f; zi = 0.f; }
        }
    };

    const int t0 = tid * PER;

    // ---- pass 1: per-thread segment product of z ----
    float ur = 1.f, ui = 0.f;
    #pragma unroll
    for (int k = 0; k < PER; k++) {
        int t = t0 + k;
        if (t < TOUT) {
            float zr, zi;
            zval(t, zr, zi);
            float nr = ur * zr - ui * zi;
            float ni = ur * zi + ui * zr;
            ur = nr; ui = ni;
        }
    }

    // ---- block-wide inclusive scan (complex multiply) ----
    float pr = ur, pi = ui;
    #pragma unroll
    for (int off = 1; off < 32; off <<= 1) {
        float orr = __shfl_up_sync(0xFFFFFFFFu, pr, off);
        float oii = __shfl_up_sync(0xFFFFFFFFu, pi, off);
        if (lane >= off) {
            float tr = orr * pr - oii * pi;
            float ti = orr * pi + oii * pr;
            pr = tr; pi = ti;
        }
    }
    if (lane == 31) wscan[warp] = make_float2(pr, pi);
    __syncthreads();
    if (tid < (THREADS / 32)) {
        float ar = wscan[tid].x, ai = wscan[tid].y;
        #pragma unroll
        for (int off = 1; off < (THREADS / 32); off <<= 1) {
            float orr = __shfl_up_sync(0xFFu, ar, off);
            float oii = __shfl_up_sync(0xFFu, ai, off);
            if (tid >= off) {
                float tr = orr * ar - oii * ai;
                float ti = orr * ai + oii * ar;
                ar = tr; ai = ti;
            }
        }
        wscan[tid] = make_float2(ar, ai);
    }
    __syncthreads();

    // thread-exclusive prefix
    float exr = __shfl_up_sync(0xFFFFFFFFu, pr, 1);
    float exi = __shfl_up_sync(0xFFFFFFFFu, pi, 1);
    if (lane == 0) { exr = 1.f; exi = 0.f; }
    if (warp > 0) {
        float2 w = wscan[warp - 1];
        float tr = w.x * exr - w.y * exi;
        float ti = w.x * exi + w.y * exr;
        exr = tr; exi = ti;
    }
    {   // renormalize prefix (|.| ~ 1)
        float n2 = exr * exr + exi * exi;
        float inv = rsqrtf(n2);
        exr *= inv; exi *= inv;
    }

    // ---- pass 2: replay segment, apply prefix, magnitude lerp -> registers ----
    float outr[PER], outi[PER];
    float ur2 = exr, ui2 = exi;
    #pragma unroll
    for (int k = 0; k < PER; k++) {
        int t = t0 + k;
        if (t < TOUT) {
            float zr, zi;
            zval(t, zr, zi);
            float nr = ur2 * zr - ui2 * zi;
            float ni = ur2 * zi + ui2 * zr;
            ur2 = nr; ui2 = ni;                      // U[t]

            float ts = (float)t * RATE;
            int j = (int)ts;
            float a = ts - (float)j;
            float2 s0 = buf[j];
            float2 s1 = buf[j + 1];
            float n0 = sqrtf(s0.x * s0.x + s0.y * s0.y);
            float n1 = sqrtf(s1.x * s1.x + s1.y * s1.y);
            float mag = a * n1 + (1.f - a) * n0;
            outr[k] = mag * ur2;
            outi[k] = mag * ui2;
        }
    }
    __syncthreads();   // input buf reads done

    // ---- stage outputs in SMEM, then coalesced store ----
    #pragma unroll
    for (int k = 0; k < PER; k++) {
        int t = t0 + k;
        if (t < TOUT) buf[t] = make_float2(outr[k], outi[k]);
    }
    __syncthreads();

    if (writeMode == 1) {
        // interleaved complex64 viewed as float32 pairs (re, im)
        float2* __restrict__ orow = (float2*)out + (size_t)row * TOUT;
        for (int i = tid; i < TOUT; i += THREADS) orow[i] = buf[i];
    } else {
        // real-only float32 output (safe fallback; in-bounds for both
        // interpretations of out_size == N_CPLX)
        float* __restrict__ orow = out + (size_t)row * TOUT;
        for (int i = tid; i < TOUT; i += THREADS) orow[i] = buf[i].x;
    }
}

extern "C" void kernel_launch(void* const* d_in, const int* in_sizes, int n_in,
                              void* d_out, int out_size) {
    const float* xr = (const float*)d_in[0];
    const float* xi = (const float*)d_in[1];
    // out_size >= 2*N_CPLX  -> float32 view of interleaved complex (re,im): full writes.
    // out_size == N_CPLX    -> ambiguous: write real-only floats (never OOB).
    int writeMode = ((long long)out_size >= 2 * N_CPLX) ? 1 : 0;
    pv_kernel<<<Bb * Fb, THREADS>>>(xr, xi, (float*)d_out, writeMode);
}

// round 3
// speedup vs baseline: 1.1462x; 1.1462x over previous
#include <cuda_runtime.h>

// Phase vocoder time-stretch, rate = 0.9, phase_advance = 0.
// out[t] = mag[t] * U[t],  U[t] = prod_{k<=t} z[k]
//   z[0]   = s[0]/|s[0]|
//   z[t>0] = normalize( s[j+1] * conj(s[j]) ),  j = floor((t-1)*0.9f)
//   mag[t] = a*|s[j1+1]| + (1-a)*|s[j1]|, j1 = floor(t*0.9f), a = frac
// Rolling 3-entry register window: j advances by {0,1} per t, and j1-j in {0,1},
// so one LDS.64 + one sqrt per step feeds both z and mag. z/mag cached in
// registers so pass 2 (prefix apply) touches no SMEM.

constexpr int Bb      = 16;
constexpr int Fb      = 1025;
constexpr int T       = 2048;
constexpr int TOUT    = 2276;          // ceil(2048 / 0.9)
constexpr int THREADS = 256;
constexpr int PER     = 9;             // 256 * 9 = 2304 >= 2276
constexpr float RATE  = 0.9f;

constexpr long long N_CPLX = (long long)Bb * Fb * TOUT;   // 37,326,400

__global__ __launch_bounds__(THREADS, 4) void pv_kernel(
    const float* __restrict__ xr, const float* __restrict__ xi,
    float* __restrict__ out, int writeMode)
{
    __shared__ __align__(16) float2 buf[2304];
    __shared__ float2 wscan[THREADS / 32];

    const int row = blockIdx.x;
    const float* __restrict__ rp = xr + (size_t)row * T;
    const float* __restrict__ ip = xi + (size_t)row * T;
    const int tid  = threadIdx.x;
    const int lane = tid & 31;
    const int warp = tid >> 5;

    // ---- stage row into SMEM (float4 LDG, row bases 8192B-aligned) ----
    {
        const float4* r4 = (const float4*)rp;
        const float4* i4 = (const float4*)ip;
        #pragma unroll
        for (int it = 0; it < (T / 4) / THREADS; it++) {
            int idx = tid + it * THREADS;
            float4 a = r4[idx];
            float4 b = i4[idx];
            int o = idx * 4;
            buf[o + 0] = make_float2(a.x, b.x);
            buf[o + 1] = make_float2(a.y, b.y);
            buf[o + 2] = make_float2(a.z, b.z);
            buf[o + 3] = make_float2(a.w, b.w);
        }
    }
    if (tid == 0) buf[T] = make_float2(0.f, 0.f);   // zero pad
    __syncthreads();

    const int t0 = tid * PER;

    // ---- pass 1: rolling window -> z[k], mag[k], local product ----
    float zr[PER], zi[PER], mg[PER];

    int p = (t0 == 0) ? 0 : (int)((float)(t0 - 1) * RATE);
    float2 a0 = buf[p], a1 = buf[p + 1], a2 = buf[p + 2];
    float m0 = sqrtf(a0.x * a0.x + a0.y * a0.y);
    float m1 = sqrtf(a1.x * a1.x + a1.y * a1.y);
    float m2 = sqrtf(a2.x * a2.x + a2.y * a2.y);

    float ur = 1.f, ui = 0.f;
    #pragma unroll
    for (int k = 0; k < PER; k++) {
        int t = t0 + k;
        if (t < TOUT) {
            int jz = (t == 0) ? 0 : (int)((float)(t - 1) * RATE);
            if (jz > p) {                    // advances by at most 1
                p = jz;
                a0 = a1; a1 = a2; a2 = buf[p + 2];
                m0 = m1; m1 = m2; m2 = sqrtf(a2.x * a2.x + a2.y * a2.y);
            }
            float pr, pq;
            if (t == 0) { pr = a0.x; pq = a0.y; }
            else {
                pr = a1.x * a0.x + a1.y * a0.y;   // s1 * conj(s0)
                pq = a1.y * a0.x - a1.x * a0.y;
            }
            float n2 = pr * pr + pq * pq;
            if (n2 > 0.f) { float inv = rsqrtf(n2); zr[k] = pr * inv; zi[k] = pq * inv; }
            else          { zr[k] = 1.f; zi[k] = 0.f; }

            float ts = (float)t * RATE;
            int jm = (int)ts;
            float al = ts - (float)jm;
            int d = jm - p;                  // 0 or 1
            float nlo = (d == 0) ? m0 : m1;
            float nhi = (d == 0) ? m1 : m2;
            mg[k] = al * nhi + (1.f - al) * nlo;

            float nr = ur * zr[k] - ui * zi[k];
            float ni = ur * zi[k] + ui * zr[k];
            ur = nr; ui = ni;
        } else {
            zr[k] = 1.f; zi[k] = 0.f; mg[k] = 0.f;
        }
    }

    // ---- block-wide inclusive scan (complex multiply) ----
    float pr = ur, pi = ui;
    #pragma unroll
    for (int off = 1; off < 32; off <<= 1) {
        float orr = __shfl_up_sync(0xFFFFFFFFu, pr, off);
        float oii = __shfl_up_sync(0xFFFFFFFFu, pi, off);
        if (lane >= off) {
            float tr = orr * pr - oii * pi;
            float ti = orr * pi + oii * pr;
            pr = tr; pi = ti;
        }
    }
    if (lane == 31) wscan[warp] = make_float2(pr, pi);
    __syncthreads();
    if (tid < (THREADS / 32)) {
        float ar = wscan[tid].x, ai = wscan[tid].y;
        #pragma unroll
        for (int off = 1; off < (THREADS / 32); off <<= 1) {
            float orr = __shfl_up_sync(0xFFu, ar, off);
            float oii = __shfl_up_sync(0xFFu, ai, off);
            if (tid >= off) {
                float tr = orr * ar - oii * ai;
                float ti = orr * ai + oii * ar;
                ar = tr; ai = ti;
            }
        }
        wscan[tid] = make_float2(ar, ai);
    }
    __syncthreads();

    // thread-exclusive prefix
    float exr = __shfl_up_sync(0xFFFFFFFFu, pr, 1);
    float exi = __shfl_up_sync(0xFFFFFFFFu, pi, 1);
    if (lane == 0) { exr = 1.f; exi = 0.f; }
    if (warp > 0) {
        float2 w = wscan[warp - 1];
        float tr = w.x * exr - w.y * exi;
        float ti = w.x * exi + w.y * exr;
        exr = tr; exi = ti;
    }
    {   // renormalize (|.| ~ 1)
        float n2 = exr * exr + exi * exi;
        float inv = rsqrtf(n2);
        exr *= inv; exi *= inv;
    }

    // ---- pass 2: pure-register prefix apply, write straight to SMEM staging ----
    // (last scan __syncthreads guarantees all buf reads are complete)
    float u_r = exr, u_i = exi;
    #pragma unroll
    for (int k = 0; k < PER; k++) {
        int t = t0 + k;
        float nr = u_r * zr[k] - u_i * zi[k];
        float ni = u_r * zi[k] + u_i * zr[k];
        u_r = nr; u_i = ni;
        if (t < TOUT) buf[t] = make_float2(mg[k] * u_r, mg[k] * u_i);
    }
    __syncthreads();

    // ---- coalesced vectorized store (row base = row*18208B, 16B-aligned) ----
    if (writeMode == 1) {
        const float4* bs = (const float4*)buf;
        float4* __restrict__ orow4 = (float4*)(out + (size_t)row * TOUT * 2);
        #pragma unroll
        for (int i = tid; i < TOUT / 2; i += THREADS) orow4[i] = bs[i];
    } else {
        float* __restrict__ orow = out + (size_t)row * TOUT;
        for (int i = tid; i < TOUT; i += THREADS) orow[i] = buf[i].x;
    }
}

extern "C" void kernel_launch(void* const* d_in, const int* in_sizes, int n_in,
                              void* d_out, int out_size) {
    const float* xr = (const float*)d_in[0];
    const float* xi = (const float*)d_in[1];
    int writeMode = ((long long)out_size >= 2 * N_CPLX) ? 1 : 0;
    pv_kernel<<<Bb * Fb, THREADS>>>(xr, xi, (float*)d_out, writeMode);
}

// round 4
// speedup vs baseline: 1.7725x; 1.5464x over previous
#include <cuda_runtime.h>

// Phase vocoder time-stretch, rate = 0.9, phase_advance = 0.
// out[t] = mag[t] * U[t],  U[t] = prod_{k<=t} z[k]
//   z[0]   = s[0]/|s[0]|
//   z[t>0] = r[jz],  r[j] = normalize(s[j+1]*conj(s[j])),  jz = floor((t-1)*0.9f)
//   mag[t] = a*nrm[jm+1] + (1-a)*nrm[jm],  jm = floor(t*0.9f), a = frac
// r[] and nrm[] are precomputed cooperatively per row (input-indexed, 2048/row),
// so the per-output loop is 3 LDS + ~10 arith with no MUFU and no predicated
// register shifting. jz(t) == jm(t-1) -> carried int, no recompute.

constexpr int Bb      = 16;
constexpr int Fb      = 1025;
constexpr int T       = 2048;
constexpr int TOUT    = 2276;          // ceil(2048 / 0.9)
constexpr int THREADS = 256;
constexpr int PER     = 9;             // 256 * 9 = 2304 >= 2276
constexpr float RATE  = 0.9f;

constexpr long long N_CPLX = (long long)Bb * Fb * TOUT;   // 37,326,400

__global__ __launch_bounds__(THREADS, 4) void pv_kernel(
    const float* __restrict__ xr, const float* __restrict__ xi,
    float* __restrict__ out, int writeMode)
{
    __shared__ __align__(16) float2 buf[2304];   // input stage, then output stage
    __shared__ __align__(16) float2 rrot[2048];  // unit rotations r[j]
    __shared__ float nrm[2052];                  // |s[j]|, j = 0..2048
    __shared__ float2 wscan[THREADS / 32];

    const int row = blockIdx.x;
    const float* __restrict__ rp = xr + (size_t)row * T;
    const float* __restrict__ ip = xi + (size_t)row * T;
    const int tid  = threadIdx.x;
    const int lane = tid & 31;
    const int warp = tid >> 5;

    // ---- stage row into SMEM (float4 LDG, bases 8192B-aligned) ----
    {
        const float4* r4 = (const float4*)rp;
        const float4* i4 = (const float4*)ip;
        #pragma unroll
        for (int it = 0; it < (T / 4) / THREADS; it++) {
            int idx = tid + it * THREADS;
            float4 a = r4[idx];
            float4 b = i4[idx];
            int o = idx * 4;
            buf[o + 0] = make_float2(a.x, b.x);
            buf[o + 1] = make_float2(a.y, b.y);
            buf[o + 2] = make_float2(a.z, b.z);
            buf[o + 3] = make_float2(a.w, b.w);
        }
    }
    if (tid == 0) { buf[T] = make_float2(0.f, 0.f); nrm[T] = 0.f; }
    __syncthreads();

    // ---- cooperative precompute: r[j], nrm[j] (coalesced, conflict-free) ----
    #pragma unroll
    for (int it = 0; it < T / THREADS; it++) {
        int j = tid + it * THREADS;
        float2 s0 = buf[j];
        float2 s1 = buf[j + 1];          // buf[T] is the zero pad
        nrm[j] = sqrtf(s0.x * s0.x + s0.y * s0.y);
        float pr = s1.x * s0.x + s1.y * s0.y;    // s1 * conj(s0)
        float pq = s1.y * s0.x - s1.x * s0.y;
        float n2 = pr * pr + pq * pq;
        float2 rv;
        if (n2 > 0.f) { float inv = rsqrtf(n2); rv = make_float2(pr * inv, pq * inv); }
        else          { rv = make_float2(1.f, 0.f); }
        rrot[j] = rv;
    }
    __syncthreads();

    const int t0 = tid * PER;

    // ---- pass 1: gather z/mag, accumulate local product ----
    float zr[PER], zi[PER], mg[PER];
    float ur = 1.f, ui = 0.f;
    float tf = (float)t0;                              // exact integer in fp32
    int jprev = (t0 == 0) ? 0 : (int)((float)(t0 - 1) * RATE);   // jm(t0-1)
    #pragma unroll
    for (int k = 0; k < PER; k++) {
        int t = t0 + k;
        if (t < TOUT) {
            float ts = tf * RATE;                      // == (float)t * 0.9f
            int jm = (int)ts;                          // trunc == floor (ts >= 0)
            float al = ts - (float)jm;

            float2 z;
            if (t == 0) {                              // z[0] = normalize(s[0])
                float2 s = buf[0];
                float n2 = s.x * s.x + s.y * s.y;
                if (n2 > 0.f) { float inv = rsqrtf(n2); z = make_float2(s.x * inv, s.y * inv); }
                else          { z = make_float2(1.f, 0.f); }
            } else {
                z = rrot[jprev];                       // jz(t) == jm(t-1)
            }
            zr[k] = z.x; zi[k] = z.y;

            float n0v = nrm[jm];
            float n1v = nrm[jm + 1];
            mg[k] = al * n1v + (1.f - al) * n0v;

            float nr = ur * z.x - ui * z.y;
            float ni = ur * z.y + ui * z.x;
            ur = nr; ui = ni;
            jprev = jm;
        } else {
            zr[k] = 1.f; zi[k] = 0.f; mg[k] = 0.f;
        }
        tf += 1.f;
    }

    // ---- block-wide inclusive scan (complex multiply) ----
    float pr = ur, pi = ui;
    #pragma unroll
    for (int off = 1; off < 32; off <<= 1) {
        float orr = __shfl_up_sync(0xFFFFFFFFu, pr, off);
        float oii = __shfl_up_sync(0xFFFFFFFFu, pi, off);
        if (lane >= off) {
            float tr = orr * pr - oii * pi;
            float ti = orr * pi + oii * pr;
            pr = tr; pi = ti;
        }
    }
    if (lane == 31) wscan[warp] = make_float2(pr, pi);
    __syncthreads();
    if (tid < (THREADS / 32)) {
        float ar = wscan[tid].x, ai = wscan[tid].y;
        #pragma unroll
        for (int off = 1; off < (THREADS / 32); off <<= 1) {
            float orr = __shfl_up_sync(0xFFu, ar, off);
            float oii = __shfl_up_sync(0xFFu, ai, off);
            if (tid >= off) {
                float tr = orr * ar - oii * ai;
                float ti = orr * ai + oii * ar;
                ar = tr; ai = ti;
            }
        }
        wscan[tid] = make_float2(ar, ai);
    }
    __syncthreads();

    // thread-exclusive prefix
    float exr = __shfl_up_sync(0xFFFFFFFFu, pr, 1);
    float exi = __shfl_up_sync(0xFFFFFFFFu, pi, 1);
    if (lane == 0) { exr = 1.f; exi = 0.f; }
    if (warp > 0) {
        float2 w = wscan[warp - 1];
        float tr = w.x * exr - w.y * exi;
        float ti = w.x * exi + w.y * exr;
        exr = tr; exi = ti;
    }
    {   // renormalize (|.| ~ 1)
        float n2 = exr * exr + exi * exi;
        float inv = rsqrtf(n2);
        exr *= inv; exi *= inv;
    }

    // ---- pass 2: pure-register prefix apply -> SMEM staging ----
    float u_r = exr, u_i = exi;
    #pragma unroll
    for (int k = 0; k < PER; k++) {
        int t = t0 + k;
        float nr = u_r * zr[k] - u_i * zi[k];
        float ni = u_r * zi[k] + u_i * zr[k];
        u_r = nr; u_i = ni;
        if (t < TOUT) buf[t] = make_float2(mg[k] * u_r, mg[k] * u_i);
    }
    __syncthreads();

    // ---- coalesced vectorized store (row base = row*18208B, 16B-aligned) ----
    if (writeMode == 1) {
        const float4* bs = (const float4*)buf;
        float4* __restrict__ orow4 = (float4*)(out + (size_t)row * TOUT * 2);
        #pragma unroll
        for (int i = tid; i < TOUT / 2; i += THREADS) orow4[i] = bs[i];
    } else {
        float* __restrict__ orow = out + (size_t)row * TOUT;
        for (int i = tid; i < TOUT; i += THREADS) orow[i] = buf[i].x;
    }
}

extern "C" void kernel_launch(void* const* d_in, const int* in_sizes, int n_in,
                              void* d_out, int out_size) {
    const float* xr = (const float*)d_in[0];
    const float* xi = (const float*)d_in[1];
    int writeMode = ((long long)out_size >= 2 * N_CPLX) ? 1 : 0;
    pv_kernel<<<Bb * Fb, THREADS>>>(xr, xi, (float*)d_out, writeMode);
}